// round 2
// baseline (speedup 1.0000x reference)
#include <cuda_runtime.h>

#define BB 8
#define SS 2048
#define HH 1024
#define NT (BB * SS)   // 16384 tokens

// Scratch (device globals — no allocation allowed in kernel_launch)
__device__ float g_ss[NT];      // score_s per token
__device__ float g_se[NT];      // score_e per token (+ bm folded in)
__device__ int   g_fl[NT];      // bit0 = start_cand, bit1 = end_cand

// Planar combined weights (coalesced loads): one float per h, 4 planes.
__device__ float g_wds[HH];     // Ws[:,1] - Ws[:,0]          (sign -> start flag)
__device__ float g_wss[HH];     // Wm0*Ws[:,0] + Wm1*Ws[:,1]  (score_s weight)
__device__ float g_wde[HH];     // We[:,1] - We[:,0]
__device__ float g_wse[HH];     // Wm2*We[:,0] + Wm3*We[:,1]
__device__ float g_bias[4];     // folded biases

// ---------------------------------------------------------------------------
// Kernel 0: fold the tiny weights into 4 planar [H] arrays + 4 scalar biases.
// ---------------------------------------------------------------------------
__global__ void __launch_bounds__(256)
prep_kernel(const float* __restrict__ Ws, const float* __restrict__ bs,
            const float* __restrict__ We, const float* __restrict__ be,
            const float* __restrict__ Wm, const float* __restrict__ bm)
{
    int h = blockIdx.x * blockDim.x + threadIdx.x;
    float wm0 = Wm[0], wm1 = Wm[1], wm2 = Wm[2], wm3 = Wm[3];
    if (h < HH) {
        float a0 = Ws[2 * h], a1 = Ws[2 * h + 1];
        float c0 = We[2 * h], c1 = We[2 * h + 1];
        g_wds[h] = a1 - a0;
        g_wss[h] = wm0 * a0 + wm1 * a1;
        g_wde[h] = c1 - c0;
        g_wse[h] = wm2 * c0 + wm3 * c1;
    }
    if (h == 0) {
        g_bias[0] = bs[1] - bs[0];                    // start diff bias
        g_bias[1] = wm0 * bs[0] + wm1 * bs[1];        // score_s bias
        g_bias[2] = be[1] - be[0];                    // end diff bias
        g_bias[3] = wm2 * be[0] + wm3 * be[1] + bm[0];// score_e bias (+bm)
    }
}

// ---------------------------------------------------------------------------
// Kernel 1: one warp per token. 4 length-1024 dots against planar weights.
// All loads coalesced: 1 streaming rep load + 4 L1-resident weight loads
// per 512B of rep per warp (5 L1tex wavefronts, was 36).
// ---------------------------------------------------------------------------
__global__ void __launch_bounds__(256)
logits_kernel(const float* __restrict__ rep,
              const int*   __restrict__ mask)
{
    int warp = (blockIdx.x * blockDim.x + threadIdx.x) >> 5;
    int lane = threadIdx.x & 31;
    if (warp >= NT) return;

    const float4* r4  = reinterpret_cast<const float4*>(rep + (size_t)warp * HH);
    const float4* wds = reinterpret_cast<const float4*>(g_wds);
    const float4* wss = reinterpret_cast<const float4*>(g_wss);
    const float4* wde = reinterpret_cast<const float4*>(g_wde);
    const float4* wse = reinterpret_cast<const float4*>(g_wse);

    float ds = 0.f, ss = 0.f, de = 0.f, se = 0.f;
    #pragma unroll
    for (int k = 0; k < HH / 128; k++) {
        int idx = k * 32 + lane;
        float4 r = __ldcs(&r4[idx]);         // streaming: don't evict weights
        float4 a = wds[idx];
        float4 b = wss[idx];
        float4 c = wde[idx];
        float4 d = wse[idx];
        ds += r.x * a.x + r.y * a.y + r.z * a.z + r.w * a.w;
        ss += r.x * b.x + r.y * b.y + r.z * b.z + r.w * b.w;
        de += r.x * c.x + r.y * c.y + r.z * c.z + r.w * c.w;
        se += r.x * d.x + r.y * d.y + r.z * d.z + r.w * d.w;
    }
    #pragma unroll
    for (int off = 16; off; off >>= 1) {
        ds += __shfl_xor_sync(0xffffffffu, ds, off);
        ss += __shfl_xor_sync(0xffffffffu, ss, off);
        de += __shfl_xor_sync(0xffffffffu, de, off);
        se += __shfl_xor_sync(0xffffffffu, se, off);
    }
    if (lane == 0) {
        int m  = (mask[warp] != 0);
        int sc = m && ((ds + g_bias[0]) >= 0.f);   // s0 <= s1
        int ec = m && ((de + g_bias[2]) >= 0.f);   // e0 <= e1
        g_ss[warp] = ss + g_bias[1];
        g_se[warp] = se + g_bias[3];
        g_fl[warp] = sc | (ec << 1);
    }
}

// ---------------------------------------------------------------------------
// Kernel 2: one block per (b, i) row; 512 threads x float4 covers S=2048 cols.
// Pure HBM-write bound (256 MB). Streaming stores, full-line 128B writes.
// ---------------------------------------------------------------------------
__global__ void __launch_bounds__(512)
pair_kernel(float* __restrict__ out_valid,
            float* __restrict__ out_masked)
{
    const int i = blockIdx.x;
    const int b = blockIdx.y;
    const int t = b * SS + i;

    const float ss = g_ss[t];
    const bool  sc = (g_fl[t] & 1);

    const size_t rowoff = ((size_t)b * SS + i) * SS;
    float4* ov = reinterpret_cast<float4*>(out_valid  + rowoff);
    float4* om = reinterpret_cast<float4*>(out_masked + rowoff);

    const int j4 = threadIdx.x;        // one float4 (4 j's) per thread
    const int j0 = j4 * 4;

    float4 v, m;
    if (!sc || (j0 + 3) < i) {
        v = make_float4(0.f, 0.f, 0.f, 0.f);
        m = v;
    } else {
        const float4 se4 = reinterpret_cast<const float4*>(g_se + b * SS)[j4];
        const int4   fl4 = reinterpret_cast<const int4*>(g_fl + b * SS)[j4];

        float ps; bool val;
        ps = ss + se4.x; val = (fl4.x & 2) && (i <= j0 + 0) && (ps > 0.f);
        v.x = val ? 1.f : 0.f; m.x = val ? ps : 0.f;
        ps = ss + se4.y; val = (fl4.y & 2) && (i <= j0 + 1) && (ps > 0.f);
        v.y = val ? 1.f : 0.f; m.y = val ? ps : 0.f;
        ps = ss + se4.z; val = (fl4.z & 2) && (i <= j0 + 2) && (ps > 0.f);
        v.z = val ? 1.f : 0.f; m.z = val ? ps : 0.f;
        ps = ss + se4.w; val = (fl4.w & 2) && (i <= j0 + 3) && (ps > 0.f);
        v.w = val ? 1.f : 0.f; m.w = val ? ps : 0.f;
    }
    __stcs(ov + j4, v);
    __stcs(om + j4, m);
}

extern "C" void kernel_launch(void* const* d_in, const int* in_sizes, int n_in,
                              void* d_out, int out_size)
{
    const float* rep  = (const float*)d_in[0];
    const int*   mask = (const int*)  d_in[1];
    const float* Ws   = (const float*)d_in[2];
    const float* bs   = (const float*)d_in[3];
    const float* We   = (const float*)d_in[4];
    const float* be   = (const float*)d_in[5];
    const float* Wm   = (const float*)d_in[6];
    const float* bm   = (const float*)d_in[7];

    float* out = (float*)d_out;
    const size_t half = (size_t)BB * SS * SS;   // valid first, masked second

    prep_kernel<<<HH / 256, 256>>>(Ws, bs, We, be, Wm, bm);
    logits_kernel<<<NT / 8, 256>>>(rep, mask);

    dim3 g2(SS, BB);
    pair_kernel<<<g2, 512>>>(out, out + half);
}

// round 3
// speedup vs baseline: 1.0948x; 1.0948x over previous
#include <cuda_runtime.h>

#define BB 8
#define SS 2048
#define HH 1024
#define NT (BB * SS)   // 16384 tokens

// Scratch (device globals — no allocation allowed in kernel_launch)
__device__ float g_ss[NT];      // score_s per token
__device__ float g_se[NT];      // score_e per token (+ bm folded in)
__device__ int   g_fl[NT];      // bit0 = start_cand, bit1 = end_cand

// ---------------------------------------------------------------------------
// Kernel 1: 512 threads = 16 warps = 16 tokens per block, 1024 blocks.
// Each block first folds the tiny weights (Ws,We,Wm,biases) into 4 planar
// smem arrays (16KB, L2-hit after the first blocks), then each warp does
// 4 length-1024 dots: 1 streaming LDG.128 of rep + 4 LDS.128 per 512B.
// DRAM-read bound: 64 MB.
// ---------------------------------------------------------------------------
__global__ void __launch_bounds__(512)
logits_kernel(const float* __restrict__ rep,
              const int*   __restrict__ mask,
              const float* __restrict__ Ws,  const float* __restrict__ bs,
              const float* __restrict__ We,  const float* __restrict__ be,
              const float* __restrict__ Wm,  const float* __restrict__ bm)
{
    __shared__ float s_wds[HH];   // Ws[:,1]-Ws[:,0]
    __shared__ float s_wss[HH];   // Wm0*Ws[:,0]+Wm1*Ws[:,1]
    __shared__ float s_wde[HH];   // We[:,1]-We[:,0]
    __shared__ float s_wse[HH];   // Wm2*We[:,0]+Wm3*We[:,1]
    __shared__ float s_bias[4];

    const int tid = threadIdx.x;
    const float wm0 = Wm[0], wm1 = Wm[1], wm2 = Wm[2], wm3 = Wm[3];

    #pragma unroll
    for (int p = 0; p < HH / 512; p++) {
        int h = p * 512 + tid;
        float a0 = Ws[2 * h], a1 = Ws[2 * h + 1];
        float c0 = We[2 * h], c1 = We[2 * h + 1];
        s_wds[h] = a1 - a0;
        s_wss[h] = wm0 * a0 + wm1 * a1;
        s_wde[h] = c1 - c0;
        s_wse[h] = wm2 * c0 + wm3 * c1;
    }
    if (tid == 0) {
        s_bias[0] = bs[1] - bs[0];
        s_bias[1] = wm0 * bs[0] + wm1 * bs[1];
        s_bias[2] = be[1] - be[0];
        s_bias[3] = wm2 * be[0] + wm3 * be[1] + bm[0];
    }
    __syncthreads();

    const int warp = blockIdx.x * 16 + (tid >> 5);   // token id
    const int lane = tid & 31;

    const float4* r4  = reinterpret_cast<const float4*>(rep + (size_t)warp * HH);
    const float4* wds = reinterpret_cast<const float4*>(s_wds);
    const float4* wss = reinterpret_cast<const float4*>(s_wss);
    const float4* wde = reinterpret_cast<const float4*>(s_wde);
    const float4* wse = reinterpret_cast<const float4*>(s_wse);

    float ds = 0.f, ss = 0.f, de = 0.f, se = 0.f;
    #pragma unroll
    for (int k = 0; k < HH / 128; k++) {
        int idx = k * 32 + lane;
        float4 r = __ldcs(&r4[idx]);         // streaming: rep is read-once
        float4 a = wds[idx];
        float4 b = wss[idx];
        float4 c = wde[idx];
        float4 d = wse[idx];
        ds += r.x * a.x + r.y * a.y + r.z * a.z + r.w * a.w;
        ss += r.x * b.x + r.y * b.y + r.z * b.z + r.w * b.w;
        de += r.x * c.x + r.y * c.y + r.z * c.z + r.w * c.w;
        se += r.x * d.x + r.y * d.y + r.z * d.z + r.w * d.w;
    }
    #pragma unroll
    for (int off = 16; off; off >>= 1) {
        ds += __shfl_xor_sync(0xffffffffu, ds, off);
        ss += __shfl_xor_sync(0xffffffffu, ss, off);
        de += __shfl_xor_sync(0xffffffffu, de, off);
        se += __shfl_xor_sync(0xffffffffu, se, off);
    }
    if (lane == 0) {
        int m  = (mask[warp] != 0);
        int sc = m && ((ds + s_bias[0]) >= 0.f);   // s0 <= s1
        int ec = m && ((de + s_bias[2]) >= 0.f);   // e0 <= e1
        g_ss[warp] = ss + s_bias[1];
        g_se[warp] = se + s_bias[3];
        g_fl[warp] = sc | (ec << 1);
    }
}

// ---------------------------------------------------------------------------
// Kernel 2: one block per (b, i) row; 512 threads x float4 covers S=2048 cols.
// Pure HBM-write bound (268 MB). Streaming stores, full-line 128B writes.
// ---------------------------------------------------------------------------
__global__ void __launch_bounds__(512)
pair_kernel(float* __restrict__ out_valid,
            float* __restrict__ out_masked)
{
    const int i = blockIdx.x;
    const int b = blockIdx.y;
    const int t = b * SS + i;

    const float ss = g_ss[t];
    const bool  sc = (g_fl[t] & 1);

    const size_t rowoff = ((size_t)b * SS + i) * SS;
    float4* ov = reinterpret_cast<float4*>(out_valid  + rowoff);
    float4* om = reinterpret_cast<float4*>(out_masked + rowoff);

    const int j4 = threadIdx.x;        // one float4 (4 j's) per thread
    const int j0 = j4 * 4;

    float4 v, m;
    if (!sc || (j0 + 3) < i) {
        v = make_float4(0.f, 0.f, 0.f, 0.f);
        m = v;
    } else {
        const float4 se4 = reinterpret_cast<const float4*>(g_se + b * SS)[j4];
        const int4   fl4 = reinterpret_cast<const int4*>(g_fl + b * SS)[j4];

        float ps; bool val;
        ps = ss + se4.x; val = (fl4.x & 2) && (i <= j0 + 0) && (ps > 0.f);
        v.x = val ? 1.f : 0.f; m.x = val ? ps : 0.f;
        ps = ss + se4.y; val = (fl4.y & 2) && (i <= j0 + 1) && (ps > 0.f);
        v.y = val ? 1.f : 0.f; m.y = val ? ps : 0.f;
        ps = ss + se4.z; val = (fl4.z & 2) && (i <= j0 + 2) && (ps > 0.f);
        v.z = val ? 1.f : 0.f; m.z = val ? ps : 0.f;
        ps = ss + se4.w; val = (fl4.w & 2) && (i <= j0 + 3) && (ps > 0.f);
        v.w = val ? 1.f : 0.f; m.w = val ? ps : 0.f;
    }
    __stcs(ov + j4, v);
    __stcs(om + j4, m);
}

extern "C" void kernel_launch(void* const* d_in, const int* in_sizes, int n_in,
                              void* d_out, int out_size)
{
    const float* rep  = (const float*)d_in[0];
    const int*   mask = (const int*)  d_in[1];
    const float* Ws   = (const float*)d_in[2];
    const float* bs   = (const float*)d_in[3];
    const float* We   = (const float*)d_in[4];
    const float* be   = (const float*)d_in[5];
    const float* Wm   = (const float*)d_in[6];
    const float* bm   = (const float*)d_in[7];

    float* out = (float*)d_out;
    const size_t half = (size_t)BB * SS * SS;   // valid first, masked second

    logits_kernel<<<NT / 16, 512>>>(rep, mask, Ws, bs, We, be, Wm, bm);

    dim3 g2(SS, BB);
    pair_kernel<<<g2, 512>>>(out, out + half);
}